// round 6
// baseline (speedup 1.0000x reference)
#include <cuda_runtime.h>
#include <cuda_fp16.h>
#include <cstdint>

#define DI __device__ __forceinline__

// scratch (device globals; no allocation allowed)
static __device__ __half2 g_wvh[32u * 512u * 256u];   // w_v half2 [b*512+l][d/2]
static __device__ __half  g_wo2[512 * 32];            // w_o packed [d8][n][4xhalf2]
static __device__ float   g_e[32 * 32 * 512];         // e     [b][n][l]
static __device__ float   g_alpha[32 * 32 * 512];     // alpha [b][n][l]
static __device__ float   g_part[32 * 4 * 32 * 512];  // vf partials [b][lc][n][d]

DI __half2 tanh2(__half2 x) {
    uint32_t r, xi = *(uint32_t*)&x;
    asm("tanh.approx.f16x2 %0, %1;" : "=r"(r) : "r"(xi));
    return *(__half2*)&r;
}
DI uint32_t f2tf(float x) { uint32_t r; asm("cvt.rna.tf32.f32 %0, %1;" : "=r"(r) : "f"(x)); return r; }
DI void mma8(float c[4], const uint32_t a[4], const uint32_t b[2]) {
    asm volatile("mma.sync.aligned.m16n8k8.row.col.f32.tf32.tf32.f32 "
                 "{%0,%1,%2,%3}, {%4,%5,%6,%7}, {%8,%9}, {%0,%1,%2,%3};"
                 : "+f"(c[0]), "+f"(c[1]), "+f"(c[2]), "+f"(c[3])
                 : "r"(a[0]), "r"(a[1]), "r"(a[2]), "r"(a[3]), "r"(b[0]), "r"(b[1]));
}
DI void cpa16(void* s, const void* g) {
    uint32_t sa = (uint32_t)__cvta_generic_to_shared(s);
    asm volatile("cp.async.ca.shared.global [%0], [%1], 16;\n" :: "r"(sa), "l"(g));
}
DI void cpcommit() { asm volatile("cp.async.commit_group;\n"); }
DI void cpwait0()  { asm volatile("cp.async.wait_group 0;\n"); }

// ---------- K1: w_o = emb @ Wo + b, packed half [d8][n][4*half2] ----------
__global__ void k1_wo(const float* __restrict__ emb, const float* __restrict__ Wo,
                      const float* __restrict__ Wob) {
    int idx = blockIdx.x * 256 + threadIdx.x;  // 4096
    int n = idx >> 7, d4 = idx & 127, d0 = d4 * 4;
    float4 a = make_float4(Wob[d0], Wob[d0+1], Wob[d0+2], Wob[d0+3]);
    const float* eb = emb + n * 512;
#pragma unroll 4
    for (int k = 0; k < 512; k++) {
        float e = __ldg(eb + k);
        float4 w = *(const float4*)(Wo + k * 512 + d0);
        a.x += e*w.x; a.y += e*w.y; a.z += e*w.z; a.w += e*w.w;
    }
    __half2 h01 = __floats2half2_rn(a.x, a.y);
    __half2 h23 = __floats2half2_rn(a.z, a.w);
    int d8 = d4 >> 1;
    uint2 v = make_uint2(*(uint32_t*)&h01, *(uint32_t*)&h23);
    ((uint2*)g_wo2)[d8 * 64 + n * 2 + (d4 & 1)] = v;
}

// ---------- K2: w_v = inp @ Wv + b (tf32 mma), 8 warps, 64x32 warp tiles (R3 config) ----------
#define AST 20
#define BST 136
__global__ __launch_bounds__(256, 2)
void k2_gemm(const float* __restrict__ A, const float* __restrict__ B,
             const float* __restrict__ bias) {
    __shared__ float As[2][128 * AST];
    __shared__ float Bs[2][16 * BST];
    __shared__ float bias_s[128];
    const int tid = threadIdx.x;
    const int bm0 = blockIdx.y * 128, bn0 = blockIdx.x * 128;
    const int warp = tid >> 5, lane = tid & 31;
    const int wm = warp >> 2, wn = warp & 3;
    const int g = lane >> 2, tig = lane & 3;
    if (tid < 128) bias_s[tid] = bias[bn0 + tid];

    auto stage = [&](int s, int k0) {
#pragma unroll
        for (int i = 0; i < 2; i++) {
            int c = tid + 256 * i;
            int r = c >> 2, cc = c & 3;
            cpa16(&As[s][r * AST + cc * 4], A + (size_t)(bm0 + r) * 512 + k0 + cc * 4);
        }
#pragma unroll
        for (int i = 0; i < 2; i++) {
            int c = tid + 256 * i;
            int r = c >> 5, cc = c & 31;
            cpa16(&Bs[s][r * BST + cc * 4], B + (size_t)(k0 + r) * 512 + bn0 + cc * 4);
        }
        cpcommit();
    };

    float c[4][4][4];
#pragma unroll
    for (int mi = 0; mi < 4; mi++)
#pragma unroll
        for (int ni = 0; ni < 4; ni++)
#pragma unroll
            for (int j = 0; j < 4; j++) c[mi][ni][j] = 0.f;

    stage(0, 0);
    for (int s = 0; s < 32; s++) {
        cpwait0();
        __syncthreads();
        if (s + 1 < 32) stage((s + 1) & 1, (s + 1) * 16);
        const int buf = s & 1;
#pragma unroll
        for (int kk = 0; kk < 16; kk += 8) {
            uint32_t af[4][4], bf[4][2];
#pragma unroll
            for (int mi = 0; mi < 4; mi++) {
                int r0 = wm * 64 + mi * 16 + g;
                af[mi][0] = f2tf(As[buf][r0 * AST + kk + tig]);
                af[mi][1] = f2tf(As[buf][(r0 + 8) * AST + kk + tig]);
                af[mi][2] = f2tf(As[buf][r0 * AST + kk + tig + 4]);
                af[mi][3] = f2tf(As[buf][(r0 + 8) * AST + kk + tig + 4]);
            }
#pragma unroll
            for (int ni = 0; ni < 4; ni++) {
                int c0 = wn * 32 + ni * 8 + g;
                bf[ni][0] = f2tf(Bs[buf][(kk + tig) * BST + c0]);
                bf[ni][1] = f2tf(Bs[buf][(kk + tig + 4) * BST + c0]);
            }
#pragma unroll
            for (int mi = 0; mi < 4; mi++)
#pragma unroll
                for (int ni = 0; ni < 4; ni++) mma8(c[mi][ni], af[mi], bf[ni]);
        }
        __syncthreads();
    }
#pragma unroll
    for (int mi = 0; mi < 4; mi++) {
        int row = bm0 + wm * 64 + mi * 16 + g;
#pragma unroll
        for (int ni = 0; ni < 4; ni++) {
            int colL = wn * 32 + ni * 8 + 2 * tig;
            float b0 = bias_s[colL], b1 = bias_s[colL + 1];
            int colh = (bn0 + colL) >> 1;
            g_wvh[(size_t)row * 256 + colh] =
                __floats2half2_rn(c[mi][ni][0] + b0, c[mi][ni][1] + b1);
            g_wvh[(size_t)(row + 8) * 256 + colh] =
                __floats2half2_rn(c[mi][ni][2] + b0, c[mi][ni][3] + b1);
        }
    }
}

// ---------- K3: e[b,n,l] = sum_d tanh(wo+wv)*We, f16x2 tanh, 4 passes/block ----------
__global__ __launch_bounds__(256)
void k3_tanh(const float* __restrict__ We) {
    __shared__ uint4 wo_s[64 * 32];   // [d8][n] : 4 half2 = 8 d  (32KB)
    __shared__ uint4 v_s[8][64];      // 8 rows x 64 uint4 (8 d each)  (8KB)
    __shared__ float we_s[512];       // 2KB
    const int b = blockIdx.y, lbase = blockIdx.x * 32, tid = threadIdx.x;
    { const uint4* s = (const uint4*)g_wo2;
#pragma unroll
      for (int i = 0; i < 8; i++) wo_s[tid + 256 * i] = s[tid + 256 * i]; }
    if (tid < 128) ((float4*)we_s)[tid] = ((const float4*)We)[tid];
    const int w = tid >> 5, n = tid & 31;
    for (int pass = 0; pass < 4; pass++) {
        const int l0 = lbase + pass * 8;
        __syncthreads();
        { const uint4* s = (const uint4*)(g_wvh + ((size_t)b * 512 + l0) * 256);
#pragma unroll
          for (int i = 0; i < 2; i++) ((uint4*)v_s)[tid + 256 * i] = s[tid + 256 * i]; }
        __syncthreads();
        float acc = 0.f;
#pragma unroll 4
        for (int d8 = 0; d8 < 64; d8++) {
            uint4 wo = wo_s[d8 * 32 + n];
            uint4 wv = v_s[w][d8];
            float4 we0 = ((const float4*)we_s)[d8 * 2];
            float4 we1 = ((const float4*)we_s)[d8 * 2 + 1];
            const __half2* wop = (const __half2*)&wo;
            const __half2* wvp = (const __half2*)&wv;
            float2 t0 = __half22float2(tanh2(__hadd2(wop[0], wvp[0])));
            float2 t1 = __half22float2(tanh2(__hadd2(wop[1], wvp[1])));
            float2 t2 = __half22float2(tanh2(__hadd2(wop[2], wvp[2])));
            float2 t3 = __half22float2(tanh2(__hadd2(wop[3], wvp[3])));
            acc = fmaf(t0.x, we0.x, acc); acc = fmaf(t0.y, we0.y, acc);
            acc = fmaf(t1.x, we0.z, acc); acc = fmaf(t1.y, we0.w, acc);
            acc = fmaf(t2.x, we1.x, acc); acc = fmaf(t2.y, we1.y, acc);
            acc = fmaf(t3.x, we1.z, acc); acc = fmaf(t3.y, we1.w, acc);
        }
        g_e[((size_t)b * 32 + n) * 512 + l0 + w] = acc;
    }
}

// ---------- K4: softmax over l, 4 rows per block ----------
__global__ __launch_bounds__(512)
void k4_softmax() {
    const int tid = threadIdx.x;
    const int rg = tid >> 7, t = tid & 127;
    const int row = blockIdx.x * 4 + rg;
    const int wid = t >> 5, lane = t & 31;
    const float* e = g_e + (size_t)row * 512;
    float* a = g_alpha + (size_t)row * 512;
    __shared__ float red[4][4];
    float4 x = ((const float4*)e)[t];
    float m = fmaxf(fmaxf(x.x, x.y), fmaxf(x.z, x.w));
#pragma unroll
    for (int o = 16; o; o >>= 1) m = fmaxf(m, __shfl_xor_sync(~0u, m, o));
    if (lane == 0) red[rg][wid] = m;
    __syncthreads();
    m = fmaxf(fmaxf(red[rg][0], red[rg][1]), fmaxf(red[rg][2], red[rg][3]));
    __syncthreads();
    x.x = __expf(x.x - m); x.y = __expf(x.y - m);
    x.z = __expf(x.z - m); x.w = __expf(x.w - m);
    float s = x.x + x.y + x.z + x.w;
#pragma unroll
    for (int o = 16; o; o >>= 1) s += __shfl_xor_sync(~0u, s, o);
    if (lane == 0) red[rg][wid] = s;
    __syncthreads();
    float inv = 1.f / (red[rg][0] + red[rg][1] + red[rg][2] + red[rg][3]);
    x.x *= inv; x.y *= inv; x.z *= inv; x.w *= inv;
    ((float4*)a)[t] = x;
}

// ---------- K5a: vf partials over 128-l chunks ----------
__global__ __launch_bounds__(128)
void k5a_vf(const float* __restrict__ inp) {
    const int b = blockIdx.x, tid = threadIdx.x;
    const int d = blockIdx.y * 128 + tid;
    const int lc = blockIdx.z, lc0 = lc * 128;
    __shared__ float a_s[32][128];
    float acc[32];
#pragma unroll
    for (int n = 0; n < 32; n++) acc[n] = 0.f;
#pragma unroll
    for (int n = 0; n < 32; n++) a_s[n][tid] = g_alpha[((size_t)b * 32 + n) * 512 + lc0 + tid];
    __syncthreads();
    const float* ib = inp + ((size_t)b * 512 + lc0) * 512 + d;
#pragma unroll 2
    for (int l4 = 0; l4 < 32; l4++) {
        float x0 = ib[(l4 * 4 + 0) * 512];
        float x1 = ib[(l4 * 4 + 1) * 512];
        float x2 = ib[(l4 * 4 + 2) * 512];
        float x3 = ib[(l4 * 4 + 3) * 512];
#pragma unroll
        for (int n = 0; n < 32; n++) {
            float4 a4 = ((const float4*)a_s[n])[l4];
            acc[n] = fmaf(a4.x, x0, acc[n]);
            acc[n] = fmaf(a4.y, x1, acc[n]);
            acc[n] = fmaf(a4.z, x2, acc[n]);
            acc[n] = fmaf(a4.w, x3, acc[n]);
        }
    }
#pragma unroll
    for (int n = 0; n < 32; n++)
        g_part[(((size_t)b * 4 + lc) * 32 + n) * 512 + d] = acc[n];
}

// ---------- K5b: reduce 4 partials -> vf ----------
__global__ __launch_bounds__(256)
void k5b_red(float* __restrict__ vf) {
    int i = blockIdx.x * 256 + threadIdx.x;
    int b = i >> 12, r = i & 4095;
    const float4* p = (const float4*)g_part;
    float4 s0 = p[(size_t)(b * 4 + 0) * 4096 + r];
    float4 s1 = p[(size_t)(b * 4 + 1) * 4096 + r];
    float4 s2 = p[(size_t)(b * 4 + 2) * 4096 + r];
    float4 s3 = p[(size_t)(b * 4 + 3) * 4096 + r];
    float4 o;
    o.x = (s0.x + s1.x) + (s2.x + s3.x);
    o.y = (s0.y + s1.y) + (s2.y + s3.y);
    o.z = (s0.z + s1.z) + (s2.z + s3.z);
    o.w = (s0.w + s1.w) + (s2.w + s3.w);
    ((float4*)vf)[i] = o;
}

// ---------- K6: logits = vf @ Wc + b, warp per row ----------
__global__ __launch_bounds__(256)
void k6_logits(const float* __restrict__ Wc, const float* __restrict__ Wcb,
               const float* __restrict__ vf, float* __restrict__ out) {
    const int tid = threadIdx.x;
    const int w = tid >> 5, lane = tid & 31;
    const int row0 = blockIdx.x * 8;
    __shared__ float v_s[8][512];
    { const float4* s = (const float4*)(vf + (size_t)row0 * 512);
#pragma unroll
      for (int i = 0; i < 4; i++) ((float4*)v_s)[tid + 256 * i] = s[tid + 256 * i]; }
    __syncthreads();
    const int row = row0 + w;
    const float* vr = v_s[w];
    float a0 = 0.f, a1 = 0.f, a2 = 0.f, a3 = 0.f;
    const int c0 = lane, c1 = lane + 32, c2 = lane + 64;
#pragma unroll 4
    for (int k = 0; k < 512; k++) {
        float v = vr[k];
        const float* wr = Wc + (size_t)k * 97;
        a0 = fmaf(v, wr[c0], a0);
        a1 = fmaf(v, wr[c1], a1);
        a2 = fmaf(v, wr[c2], a2);
        if (lane == 0) a3 = fmaf(v, wr[96], a3);
    }
    float* orow = out + (size_t)row * 97;
    orow[c0] = a0 + Wcb[c0];
    orow[c1] = a1 + Wcb[c1];
    orow[c2] = a2 + Wcb[c2];
    if (lane == 0) orow[96] = a3 + Wcb[96];
}

extern "C" void kernel_launch(void* const* d_in, const int* in_sizes, int n_in,
                              void* d_out, int out_size) {
    const float* inp  = (const float*)d_in[0];
    const float* emb  = (const float*)d_in[1];
    const float* Wo_w = (const float*)d_in[2];
    const float* Wo_b = (const float*)d_in[3];
    const float* Wv_w = (const float*)d_in[4];
    const float* Wv_b = (const float*)d_in[5];
    const float* We_w = (const float*)d_in[6];
    const float* Wc_w = (const float*)d_in[8];
    const float* Wc_b = (const float*)d_in[9];
    float* out = (float*)d_out;
    float* vf = out;                         // (32*32, 512)
    float* logits = out + 32 * 32 * 512;     // (32*32, 97)

    k1_wo<<<16, 256>>>(emb, Wo_w, Wo_b);
    k2_gemm<<<dim3(4, 128), 256>>>(inp, Wv_w, Wv_b);
    k3_tanh<<<dim3(16, 32), 256>>>(We_w);
    k4_softmax<<<256, 512>>>();
    k5a_vf<<<dim3(32, 4, 4), 128>>>(inp);
    k5b_red<<<512, 256>>>(vf);
    k6_logits<<<128, 256>>>(Wc_w, Wc_b, vf, logits);
}

// round 7
// speedup vs baseline: 1.1761x; 1.1761x over previous
#include <cuda_runtime.h>
#include <cuda_fp16.h>
#include <cstdint>

#define DI __device__ __forceinline__

// scratch (device globals; no allocation allowed)
static __device__ __half  g_wo2[512 * 32];              // w_o packed [d8][n][4xhalf2]
static __device__ float   g_epart[4u * 32u * 512u * 32u]; // e partials [dc][b][l][n]
static __device__ float   g_alpha[32u * 512u * 32u];    // alpha [b][l][n]
static __device__ float   g_part[32 * 4 * 32 * 512];    // vf partials [b][lc][n][d]

DI __half2 tanh2(__half2 x) {
    uint32_t r, xi = *(uint32_t*)&x;
    asm("tanh.approx.f16x2 %0, %1;" : "=r"(r) : "r"(xi));
    return *(__half2*)&r;
}
DI uint32_t f2tf(float x) { uint32_t r; asm("cvt.rna.tf32.f32 %0, %1;" : "=r"(r) : "f"(x)); return r; }
DI void mma8(float c[4], const uint32_t a[4], const uint32_t b[2]) {
    asm volatile("mma.sync.aligned.m16n8k8.row.col.f32.tf32.tf32.f32 "
                 "{%0,%1,%2,%3}, {%4,%5,%6,%7}, {%8,%9}, {%0,%1,%2,%3};"
                 : "+f"(c[0]), "+f"(c[1]), "+f"(c[2]), "+f"(c[3])
                 : "r"(a[0]), "r"(a[1]), "r"(a[2]), "r"(a[3]), "r"(b[0]), "r"(b[1]));
}
DI void cpa16(void* s, const void* g) {
    uint32_t sa = (uint32_t)__cvta_generic_to_shared(s);
    asm volatile("cp.async.ca.shared.global [%0], [%1], 16;\n" :: "r"(sa), "l"(g));
}
DI void cpcommit() { asm volatile("cp.async.commit_group;\n"); }
DI void cpwait0()  { asm volatile("cp.async.wait_group 0;\n"); }

// ---------- K1: w_o = emb @ Wo + b, packed half [d8][n][4*half2] ----------
__global__ void k1_wo(const float* __restrict__ emb, const float* __restrict__ Wo,
                      const float* __restrict__ Wob) {
    int idx = blockIdx.x * 256 + threadIdx.x;  // 4096
    int n = idx >> 7, d4 = idx & 127, d0 = d4 * 4;
    float4 a = make_float4(Wob[d0], Wob[d0+1], Wob[d0+2], Wob[d0+3]);
    const float* eb = emb + n * 512;
#pragma unroll 4
    for (int k = 0; k < 512; k++) {
        float e = __ldg(eb + k);
        float4 w = *(const float4*)(Wo + k * 512 + d0);
        a.x += e*w.x; a.y += e*w.y; a.z += e*w.z; a.w += e*w.w;
    }
    __half2 h01 = __floats2half2_rn(a.x, a.y);
    __half2 h23 = __floats2half2_rn(a.z, a.w);
    int d8 = d4 >> 1;
    uint2 v = make_uint2(*(uint32_t*)&h01, *(uint32_t*)&h23);
    ((uint2*)g_wo2)[d8 * 64 + n * 2 + (d4 & 1)] = v;
}

// ---------- K23: w_v = inp @ Wv + b (tf32 mma) FUSED with tanh/We reduction ----------
// grid (4=d-chunk, 128=row-chunk), 256 threads, 8 warps, warp tile 64x32.
// Epilogue: partial e over this block's 128 d, written to g_epart[dc][b][l][n].
#define AST 20
#define BST 136
#define VST 68   // v_s row stride in half2 units (4g+tig bank-unique)
__global__ __launch_bounds__(256, 2)
void k23_gemm_tanh(const float* __restrict__ A, const float* __restrict__ B,
                   const float* __restrict__ bias, const float* __restrict__ We) {
    // unioned smem: mainloop (As 20480B | Bs 17408B) vs epilogue (v_s 34816B | wo_s 8192B | we_s 512B)
    __shared__ __align__(16) char sraw[43520];
    float*    As   = (float*)sraw;              // [2][128*AST]
    float*    Bs   = (float*)(sraw + 20480);    // [2][16*BST]
    uint32_t* v_s  = (uint32_t*)sraw;           // [128*VST] half2 bits
    uint4*    wo_s = (uint4*)(sraw + 34816);    // [16*32]
    float*    we_s = (float*)(sraw + 43008);    // [128]
    __shared__ float bias_s[128];

    const int tid = threadIdx.x;
    const int bm0 = blockIdx.y * 128, bn0 = blockIdx.x * 128;
    const int warp = tid >> 5, lane = tid & 31;
    const int wm = warp >> 2, wn = warp & 3;
    const int g = lane >> 2, tig = lane & 3;
    if (tid < 128) bias_s[tid] = bias[bn0 + tid];

    auto stage = [&](int s, int k0) {
#pragma unroll
        for (int i = 0; i < 2; i++) {
            int c = tid + 256 * i;
            int r = c >> 2, cc = c & 3;
            cpa16(&As[s * 2560 + r * AST + cc * 4], A + (size_t)(bm0 + r) * 512 + k0 + cc * 4);
        }
#pragma unroll
        for (int i = 0; i < 2; i++) {
            int c = tid + 256 * i;
            int r = c >> 5, cc = c & 31;
            cpa16(&Bs[s * 2176 + r * BST + cc * 4], B + (size_t)(k0 + r) * 512 + bn0 + cc * 4);
        }
        cpcommit();
    };

    float c[4][4][4];
#pragma unroll
    for (int mi = 0; mi < 4; mi++)
#pragma unroll
        for (int ni = 0; ni < 4; ni++)
#pragma unroll
            for (int j = 0; j < 4; j++) c[mi][ni][j] = 0.f;

    stage(0, 0);
    for (int s = 0; s < 32; s++) {
        cpwait0();
        __syncthreads();
        if (s + 1 < 32) stage((s + 1) & 1, (s + 1) * 16);
        const int buf = s & 1;
#pragma unroll
        for (int kk = 0; kk < 16; kk += 8) {
            uint32_t af[4][4], bf[4][2];
#pragma unroll
            for (int mi = 0; mi < 4; mi++) {
                int r0 = wm * 64 + mi * 16 + g;
                af[mi][0] = f2tf(As[buf * 2560 + r0 * AST + kk + tig]);
                af[mi][1] = f2tf(As[buf * 2560 + (r0 + 8) * AST + kk + tig]);
                af[mi][2] = f2tf(As[buf * 2560 + r0 * AST + kk + tig + 4]);
                af[mi][3] = f2tf(As[buf * 2560 + (r0 + 8) * AST + kk + tig + 4]);
            }
#pragma unroll
            for (int ni = 0; ni < 4; ni++) {
                int c0 = wn * 32 + ni * 8 + g;
                bf[ni][0] = f2tf(Bs[buf * 2176 + (kk + tig) * BST + c0]);
                bf[ni][1] = f2tf(Bs[buf * 2176 + (kk + tig + 4) * BST + c0]);
            }
#pragma unroll
            for (int mi = 0; mi < 4; mi++)
#pragma unroll
                for (int ni = 0; ni < 4; ni++) mma8(c[mi][ni], af[mi], bf[ni]);
        }
        __syncthreads();   // after this, As/Bs reads complete -> safe to alias
    }

    // ---- epilogue phase 1: stage wo/We tiles + fragments (as half2) into smem ----
    {
        const uint4* wog = (const uint4*)g_wo2;   // [64*32]
        int d8base = bn0 >> 3;                     // 16 local d8 groups
        wo_s[tid]       = wog[(d8base + (tid >> 5)) * 32 + lane];
        wo_s[tid + 256] = wog[(d8base + 8 + (tid >> 5)) * 32 + lane];
        if (tid < 32) ((float4*)we_s)[tid] = ((const float4*)(We + bn0))[tid];
    }
#pragma unroll
    for (int mi = 0; mi < 4; mi++) {
        int r = wm * 64 + mi * 16 + g;
#pragma unroll
        for (int ni = 0; ni < 4; ni++) {
            int colL = wn * 32 + ni * 8 + 2 * tig;
            float b0 = bias_s[colL], b1 = bias_s[colL + 1];
            int d2 = wn * 16 + ni * 4 + tig;
            __half2 h0 = __floats2half2_rn(c[mi][ni][0] + b0, c[mi][ni][1] + b1);
            __half2 h1 = __floats2half2_rn(c[mi][ni][2] + b0, c[mi][ni][3] + b1);
            v_s[r * VST + d2]       = *(uint32_t*)&h0;
            v_s[(r + 8) * VST + d2] = *(uint32_t*)&h1;
        }
    }
    __syncthreads();

    // ---- epilogue phase 2: e_partial[l][n] = sum over local d of tanh(wo+wv)*We ----
    const int bq = bm0 >> 9;          // batch
    const int l0 = bm0 & 511;         // l offset of this row-chunk
    const int n = lane;
    float* ep = g_epart + (((size_t)blockIdx.x * 32 + bq) * 512 + l0) * 32;
#pragma unroll 2
    for (int li = 0; li < 16; li++) {
        int l = warp * 16 + li;
        float acc = 0.f;
#pragma unroll 4
        for (int d8 = 0; d8 < 16; d8++) {
            uint4 wo = wo_s[d8 * 32 + n];
            uint4 wv = *(const uint4*)&v_s[l * VST + d8 * 4];
            float4 we0 = ((const float4*)we_s)[d8 * 2];
            float4 we1 = ((const float4*)we_s)[d8 * 2 + 1];
            const __half2* wop = (const __half2*)&wo;
            const __half2* wvp = (const __half2*)&wv;
            float2 t0 = __half22float2(tanh2(__hadd2(wop[0], wvp[0])));
            float2 t1 = __half22float2(tanh2(__hadd2(wop[1], wvp[1])));
            float2 t2 = __half22float2(tanh2(__hadd2(wop[2], wvp[2])));
            float2 t3 = __half22float2(tanh2(__hadd2(wop[3], wvp[3])));
            acc = fmaf(t0.x, we0.x, acc); acc = fmaf(t0.y, we0.y, acc);
            acc = fmaf(t1.x, we0.z, acc); acc = fmaf(t1.y, we0.w, acc);
            acc = fmaf(t2.x, we1.x, acc); acc = fmaf(t2.y, we1.y, acc);
            acc = fmaf(t3.x, we1.z, acc); acc = fmaf(t3.y, we1.w, acc);
        }
        ep[(size_t)l * 32 + n] = acc;   // lanes n consecutive -> coalesced
    }
}

// ---------- K4: e = sum of 4 d-chunk partials, softmax over l, alpha [b][l][n] ----------
__global__ __launch_bounds__(512)
void k4_softmax() {
    const int b = blockIdx.x, tid = threadIdx.x;
    const int w = tid >> 5, n = tid & 31;      // 16 warps, each 32 l
    const float* e0 = g_epart + ((size_t)b * 512) * 32;
    const size_t dstr = (size_t)32 * 512 * 32;
    __shared__ float red[16][32];
    float ev[32];
    float m = -1e30f;
#pragma unroll 4
    for (int i = 0; i < 32; i++) {
        size_t idx = (size_t)(w * 32 + i) * 32 + n;
        float e = (e0[idx] + e0[idx + dstr]) + (e0[idx + 2 * dstr] + e0[idx + 3 * dstr]);
        ev[i] = e; m = fmaxf(m, e);
    }
    red[w][n] = m; __syncthreads();
#pragma unroll
    for (int ww = 0; ww < 16; ww++) m = fmaxf(m, red[ww][n]);
    __syncthreads();
    float s = 0.f;
#pragma unroll 4
    for (int i = 0; i < 32; i++) { ev[i] = __expf(ev[i] - m); s += ev[i]; }
    red[w][n] = s; __syncthreads();
    s = 0.f;
#pragma unroll
    for (int ww = 0; ww < 16; ww++) s += red[ww][n];
    float inv = 1.f / s;
    float* a = g_alpha + ((size_t)b * 512) * 32;
#pragma unroll 4
    for (int i = 0; i < 32; i++) a[(size_t)(w * 32 + i) * 32 + n] = ev[i] * inv;
}

// ---------- K5a: vf partials over 128-l chunks (alpha [b][l][n]) ----------
__global__ __launch_bounds__(128)
void k5a_vf(const float* __restrict__ inp) {
    const int b = blockIdx.x, tid = threadIdx.x;
    const int d = blockIdx.y * 128 + tid;
    const int lc = blockIdx.z, lc0 = lc * 128;
    __shared__ float a_s[128][32];   // [l][n] 16KB
    { const float4* ga = (const float4*)(g_alpha + ((size_t)b * 512 + lc0) * 32);
      float4* sa = (float4*)a_s;
#pragma unroll
      for (int i = 0; i < 8; i++) sa[tid + 128 * i] = ga[tid + 128 * i]; }
    __syncthreads();
    float acc[32];
#pragma unroll
    for (int n = 0; n < 32; n++) acc[n] = 0.f;
    const float* ib = inp + ((size_t)b * 512 + lc0) * 512 + d;
#pragma unroll 4
    for (int l = 0; l < 128; l++) {
        float x = ib[(size_t)l * 512];
        const float4* ar = (const float4*)a_s[l];
#pragma unroll
        for (int n8 = 0; n8 < 8; n8++) {
            float4 a4 = ar[n8];
            acc[n8 * 4 + 0] = fmaf(a4.x, x, acc[n8 * 4 + 0]);
            acc[n8 * 4 + 1] = fmaf(a4.y, x, acc[n8 * 4 + 1]);
            acc[n8 * 4 + 2] = fmaf(a4.z, x, acc[n8 * 4 + 2]);
            acc[n8 * 4 + 3] = fmaf(a4.w, x, acc[n8 * 4 + 3]);
        }
    }
#pragma unroll
    for (int n = 0; n < 32; n++)
        g_part[(((size_t)b * 4 + lc) * 32 + n) * 512 + d] = acc[n];
}

// ---------- K5b: reduce 4 partials -> vf ----------
__global__ __launch_bounds__(256)
void k5b_red(float* __restrict__ vf) {
    int i = blockIdx.x * 256 + threadIdx.x;
    int b = i >> 12, r = i & 4095;
    const float4* p = (const float4*)g_part;
    float4 s0 = p[(size_t)(b * 4 + 0) * 4096 + r];
    float4 s1 = p[(size_t)(b * 4 + 1) * 4096 + r];
    float4 s2 = p[(size_t)(b * 4 + 2) * 4096 + r];
    float4 s3 = p[(size_t)(b * 4 + 3) * 4096 + r];
    float4 o;
    o.x = (s0.x + s1.x) + (s2.x + s3.x);
    o.y = (s0.y + s1.y) + (s2.y + s3.y);
    o.z = (s0.z + s1.z) + (s2.z + s3.z);
    o.w = (s0.w + s1.w) + (s2.w + s3.w);
    ((float4*)vf)[i] = o;
}

// ---------- K6: logits = vf @ Wc + b, warp per row ----------
__global__ __launch_bounds__(256)
void k6_logits(const float* __restrict__ Wc, const float* __restrict__ Wcb,
               const float* __restrict__ vf, float* __restrict__ out) {
    const int tid = threadIdx.x;
    const int w = tid >> 5, lane = tid & 31;
    const int row0 = blockIdx.x * 8;
    __shared__ float v_s[8][512];
    { const float4* s = (const float4*)(vf + (size_t)row0 * 512);
#pragma unroll
      for (int i = 0; i < 4; i++) ((float4*)v_s)[tid + 256 * i] = s[tid + 256 * i]; }
    __syncthreads();
    const int row = row0 + w;
    const float* vr = v_s[w];
    float a0 = 0.f, a1 = 0.f, a2 = 0.f, a3 = 0.f;
    const int c0 = lane, c1 = lane + 32, c2 = lane + 64;
#pragma unroll 4
    for (int k = 0; k < 512; k++) {
        float v = vr[k];
        const float* wr = Wc + (size_t)k * 97;
        a0 = fmaf(v, wr[c0], a0);
        a1 = fmaf(v, wr[c1], a1);
        a2 = fmaf(v, wr[c2], a2);
        if (lane == 0) a3 = fmaf(v, wr[96], a3);
    }
    float* orow = out + (size_t)row * 97;
    orow[c0] = a0 + Wcb[c0];
    orow[c1] = a1 + Wcb[c1];
    orow[c2] = a2 + Wcb[c2];
    if (lane == 0) orow[96] = a3 + Wcb[96];
}

extern "C" void kernel_launch(void* const* d_in, const int* in_sizes, int n_in,
                              void* d_out, int out_size) {
    const float* inp  = (const float*)d_in[0];
    const float* emb  = (const float*)d_in[1];
    const float* Wo_w = (const float*)d_in[2];
    const float* Wo_b = (const float*)d_in[3];
    const float* Wv_w = (const float*)d_in[4];
    const float* Wv_b = (const float*)d_in[5];
    const float* We_w = (const float*)d_in[6];
    const float* Wc_w = (const float*)d_in[8];
    const float* Wc_b = (const float*)d_in[9];
    float* out = (float*)d_out;
    float* vf = out;                         // (32*32, 512)
    float* logits = out + 32 * 32 * 512;     // (32*32, 97)

    k1_wo<<<16, 256>>>(emb, Wo_w, Wo_b);
    k23_gemm_tanh<<<dim3(4, 128), 256>>>(inp, Wv_w, Wv_b, We_w);
    k4_softmax<<<32, 512>>>();
    k5a_vf<<<dim3(32, 4, 4), 128>>>(inp);
    k5b_red<<<512, 256>>>(vf);
    k6_logits<<<128, 256>>>(Wc_w, Wc_b, vf, logits);
}